// round 8
// baseline (speedup 1.0000x reference)
#include <cuda_runtime.h>
#include <cstdint>

// Problem constants (shapes fixed by the dataset)
#define BSZ 4096
#define DD  512
#define HH  1024
#define TW  16
#define NEL (BSZ * HH)   // 4,194,304 = 2^22

// GEMM tiling
#define BM 128
#define BN 128
#define BK 16
#define TM 8
#define TN 8
#define NTHR 256

// ---------------------------------------------------------------------------
// Scratch (static device globals — no runtime allocation)
// ---------------------------------------------------------------------------
__device__ float g_z0[NEL];   // fc1(x), time-invariant
__device__ float g_c0[NEL];   // z0 @ lif1_win.T, time-invariant
__device__ float g_v1[NEL];
__device__ float g_i1[NEL];
__device__ float g_z1a[NEL];
__device__ float g_z1b[NEL];
__device__ float g_G2[NEL];
__device__ float g_v2[NEL];
__device__ float g_i2[NEL];
__device__ float g_z2a[NEL];
__device__ float g_z2b[NEL];
__device__ unsigned g_cnt[TW];

// ---------------------------------------------------------------------------
__global__ void init_state() {
    size_t i = (size_t)blockIdx.x * blockDim.x + threadIdx.x;
    size_t stride = (size_t)gridDim.x * blockDim.x;
    for (size_t k = i; k < (size_t)NEL; k += stride) {
        g_v1[k] = 0.f; g_i1[k] = 0.f; g_z1a[k] = 0.f;
        g_v2[k] = 0.f; g_i2[k] = 0.f; g_z2a[k] = 0.f;
    }
    if (i < TW) g_cnt[i] = 0u;
}

// ---------------------------------------------------------------------------
// Fused SGEMM:  C[M,N] = A1[M,K1] @ W1[N,K1]^T  (+ A2[M,K2] @ W2[N,K2]^T)
// mode 0: Cout = acc (+ bias[n])
// mode 1: LIF1 epilogue (cin = hoisted constant input current)
// mode 2: LIF2 epilogue (dual-GEMM) + spike count
//
// Double-buffered smem pipeline: one __syncthreads per k-tile; global-load
// latency for tile t+1 is hidden behind the 1024-FMA compute of tile t.
// FMA order per output element is identical to the R3 kernel (bit-exact).
// ---------------------------------------------------------------------------
__global__ __launch_bounds__(NTHR, 2)
void sgemm_fused(const float* __restrict__ A1, const float* __restrict__ W1,
                 const float* __restrict__ A2, const float* __restrict__ W2,
                 const float* __restrict__ bias, const float* __restrict__ cin,
                 float* __restrict__ Cout,
                 float* __restrict__ Vst, float* __restrict__ Ist,
                 unsigned* __restrict__ cnt,
                 int K1, int K2, int N, int mode)
{
    __shared__ __align__(16) float As[2][BK][BM + 4];
    __shared__ __align__(16) float Bs[2][BK][BN + 4];

    const int tid = threadIdx.x;
    const int bn = blockIdx.x;
    const int bm = blockIdx.y;
    const int tx = tid & 15;         // 0..15 -> N microtile
    const int ty = tid >> 4;         // 0..15 -> M microtile
    const int lrow = tid >> 2;       // 0..63 loader row
    const int lcol = (tid & 3) << 2; // 0,4,8,12 loader col (float4)

    float acc[TM][TN];
#pragma unroll
    for (int i = 0; i < TM; ++i)
#pragma unroll
        for (int j = 0; j < TN; ++j) acc[i][j] = 0.f;

    const int nt1 = K1 / BK;
    const int ntot = nt1 + (A2 ? (K2 / BK) : 0);

    float4 ra0, ra1, rb0, rb1;   // staging registers

    // ---- loader helpers ----
    #define LDG_TILE(kt)                                                       \
        do {                                                                   \
            const float* A_; const float* W_; int k0_, K_;                     \
            if ((kt) < nt1) { A_ = A1; W_ = W1; k0_ = (kt) * BK; K_ = K1; }    \
            else { A_ = A2; W_ = W2; k0_ = ((kt) - nt1) * BK; K_ = K2; }       \
            const float* Ap = A_ + (size_t)(bm * BM + lrow) * K_ + k0_ + lcol; \
            const float* Wp = W_ + (size_t)(bn * BN + lrow) * K_ + k0_ + lcol; \
            ra0 = *(const float4*)Ap;                                          \
            ra1 = *(const float4*)(Ap + (size_t)64 * K_);                      \
            rb0 = *(const float4*)Wp;                                          \
            rb1 = *(const float4*)(Wp + (size_t)64 * K_);                      \
        } while (0)

    #define STS_TILE(buf)                                                      \
        do {                                                                   \
            As[buf][lcol + 0][lrow] = ra0.x; As[buf][lcol + 1][lrow] = ra0.y;  \
            As[buf][lcol + 2][lrow] = ra0.z; As[buf][lcol + 3][lrow] = ra0.w;  \
            As[buf][lcol + 0][lrow + 64] = ra1.x;                              \
            As[buf][lcol + 1][lrow + 64] = ra1.y;                              \
            As[buf][lcol + 2][lrow + 64] = ra1.z;                              \
            As[buf][lcol + 3][lrow + 64] = ra1.w;                              \
            Bs[buf][lcol + 0][lrow] = rb0.x; Bs[buf][lcol + 1][lrow] = rb0.y;  \
            Bs[buf][lcol + 2][lrow] = rb0.z; Bs[buf][lcol + 3][lrow] = rb0.w;  \
            Bs[buf][lcol + 0][lrow + 64] = rb1.x;                              \
            Bs[buf][lcol + 1][lrow + 64] = rb1.y;                              \
            Bs[buf][lcol + 2][lrow + 64] = rb1.z;                              \
            Bs[buf][lcol + 3][lrow + 64] = rb1.w;                              \
        } while (0)

    // ---- prologue: stage tile 0 ----
    LDG_TILE(0);
    STS_TILE(0);
    __syncthreads();

    for (int kt = 0; kt < ntot; ++kt) {
        const int cur = kt & 1;
        const bool more = (kt + 1 < ntot);

        if (more) LDG_TILE(kt + 1);   // in flight during compute below

#pragma unroll
        for (int k = 0; k < BK; ++k) {
            const float4 av0 = *(const float4*)&As[cur][k][ty * TM];
            const float4 av1 = *(const float4*)&As[cur][k][ty * TM + 4];
            const float4 bv0 = *(const float4*)&Bs[cur][k][tx * TN];
            const float4 bv1 = *(const float4*)&Bs[cur][k][tx * TN + 4];
            float a[TM] = {av0.x, av0.y, av0.z, av0.w,
                           av1.x, av1.y, av1.z, av1.w};
            float b[TN] = {bv0.x, bv0.y, bv0.z, bv0.w,
                           bv1.x, bv1.y, bv1.z, bv1.w};
#pragma unroll
            for (int i = 0; i < TM; ++i)
#pragma unroll
                for (int j = 0; j < TN; ++j)
                    acc[i][j] += a[i] * b[j];
        }

        if (more) {
            STS_TILE(cur ^ 1);   // buffer last read at kt-1: all warps passed
            __syncthreads();     // the previous barrier after finishing it
        }
    }

    // ---------------- epilogue ----------------
    const int m0 = bm * BM + ty * TM;
    const int n0 = bn * BN + tx * TN;

    if (mode == 0) {
#pragma unroll
        for (int i = 0; i < TM; ++i) {
            size_t row = (size_t)(m0 + i) * N + n0;
#pragma unroll
            for (int j = 0; j < TN; ++j) {
                float v = acc[i][j];
                if (bias) v += bias[n0 + j];
                Cout[row + j] = v;
            }
        }
    } else {
        unsigned spikes = 0;
#pragma unroll
        for (int i = 0; i < TM; ++i) {
            size_t row = (size_t)(m0 + i) * N + n0;
#pragma unroll
            for (int j = 0; j < TN; ++j) {
                size_t idx = row + j;
                float vold = Vst[idx];
                float iold = Ist[idx];
                float vdec = vold + 0.1f * (iold - vold);     // dt*tau_mem_inv
                float z = (vdec > 1.0f) ? 1.0f : 0.0f;        // v_th = 1
                Vst[idx] = (1.0f - z) * vdec;                 // v_reset = 0
                float idec = iold * 0.8f;                     // 1 - dt*tau_syn_inv
                float inew = (mode == 1) ? ((idec + cin[idx]) + acc[i][j])
                                         : (idec + acc[i][j]);
                Ist[idx] = inew;
                Cout[idx] = z;
                spikes += (unsigned)z;
            }
        }
        if (mode == 2) {
#pragma unroll
            for (int o = 16; o; o >>= 1)
                spikes += __shfl_xor_sync(0xFFFFFFFFu, spikes, o);
            if ((tid & 31) == 0) atomicAdd(cnt, spikes);
        }
    }
}

// ---------------------------------------------------------------------------
// Final: copy last z2 to output, compute firing-rate scalar (bit-exact:
// counts are integers, mean = count * 2^-22, sum in scan order, * 1/16).
// ---------------------------------------------------------------------------
__global__ void finalize(const float* __restrict__ zlast,
                         const unsigned* __restrict__ cnt,
                         float* __restrict__ out, int n, int out_size)
{
    size_t i = (size_t)blockIdx.x * blockDim.x + threadIdx.x;
    size_t stride = (size_t)gridDim.x * blockDim.x;
    for (size_t k = i; k < (size_t)n; k += stride) out[k] = zlast[k];
    if (i == 0 && out_size > n) {
        float rs = 0.f;
        for (int t = 0; t < TW; ++t)
            rs += (float)cnt[t] * (1.0f / 4194304.0f);   // exact: /2^22
        out[n] = rs * (1.0f / 16.0f);                     // inv_T, exact
    }
}

// ---------------------------------------------------------------------------
extern "C" void kernel_launch(void* const* d_in, const int* in_sizes, int n_in,
                              void* d_out, int out_size)
{
    const float* x     = (const float*)d_in[0];
    const float* fc1w  = (const float*)d_in[1];
    const float* fc1b  = (const float*)d_in[2];
    const float* w1in  = (const float*)d_in[3];
    const float* w1rec = (const float*)d_in[4];
    const float* fc2w  = (const float*)d_in[5];
    const float* fc2b  = (const float*)d_in[6];
    const float* w2in  = (const float*)d_in[7];
    const float* w2rec = (const float*)d_in[8];
    (void)in_sizes; (void)n_in;

    float *z0, *c0, *v1, *i1, *z1a, *z1b, *G2, *v2, *i2, *z2a, *z2b;
    unsigned* cnt;
    cudaGetSymbolAddress((void**)&z0,  g_z0);
    cudaGetSymbolAddress((void**)&c0,  g_c0);
    cudaGetSymbolAddress((void**)&v1,  g_v1);
    cudaGetSymbolAddress((void**)&i1,  g_i1);
    cudaGetSymbolAddress((void**)&z1a, g_z1a);
    cudaGetSymbolAddress((void**)&z1b, g_z1b);
    cudaGetSymbolAddress((void**)&G2,  g_G2);
    cudaGetSymbolAddress((void**)&v2,  g_v2);
    cudaGetSymbolAddress((void**)&i2,  g_i2);
    cudaGetSymbolAddress((void**)&z2a, g_z2a);
    cudaGetSymbolAddress((void**)&z2b, g_z2b);
    cudaGetSymbolAddress((void**)&cnt, g_cnt);

    dim3 grid(HH / BN, BSZ / BM);   // (8, 32) = 256 blocks, single wave

    init_state<<<256, 256>>>();

    // z0 = x @ fc1_w^T + fc1_b   (K = 512)
    sgemm_fused<<<grid, NTHR>>>(x, fc1w, nullptr, nullptr, fc1b, nullptr,
                                z0, nullptr, nullptr, nullptr,
                                DD, 0, HH, 0);
    // c0 = z0 @ lif1_win^T       (time-invariant input current, hoisted)
    sgemm_fused<<<grid, NTHR>>>(z0, w1in, nullptr, nullptr, nullptr, nullptr,
                                c0, nullptr, nullptr, nullptr,
                                HH, 0, HH, 0);

    for (int t = 0; t < TW; ++t) {
        float* z1o = (t & 1) ? z1b : z1a;
        float* z1n = (t & 1) ? z1a : z1b;
        float* z2o = (t & 1) ? z2b : z2a;
        float* z2n = (t & 1) ? z2a : z2b;

        // LIF1: acc = z1_old @ w1rec^T ; epilogue: decay/spike/reset,
        //       i1 = (0.8*i1 + c0) + acc, writes z1_new
        sgemm_fused<<<grid, NTHR>>>(z1o, w1rec, nullptr, nullptr, nullptr, c0,
                                    z1n, v1, i1, nullptr,
                                    HH, 0, HH, 1);
        // G2 = z1_new @ fc2_w^T + fc2_b
        sgemm_fused<<<grid, NTHR>>>(z1n, fc2w, nullptr, nullptr, fc2b, nullptr,
                                    G2, nullptr, nullptr, nullptr,
                                    HH, 0, HH, 0);
        // LIF2: acc = G2 @ w2in^T + z2_old @ w2rec^T (dual-K GEMM);
        //       epilogue updates v2/i2, writes z2_new, counts spikes
        sgemm_fused<<<grid, NTHR>>>(G2, w2in, z2o, w2rec, nullptr, nullptr,
                                    z2n, v2, i2, cnt + t,
                                    HH, HH, HH, 2);
    }

    // t = 15 (odd) wrote z2_new into z2a
    finalize<<<512, 256>>>(z2a, cnt, (float*)d_out, NEL, out_size);
}

// round 11
// speedup vs baseline: 2.1977x; 2.1977x over previous
#include <cuda_runtime.h>
#include <cstdint>

#define BSZ 4096
#define DD  512
#define HH  1024
#define TW  16
#define NEL (BSZ * HH)

#define BM 128
#define BN 128
#define BK 16
#define TM 8
#define TN 8
#define NTHR 256
#define FULLMASK 0xFFFFFFFFu

// ---------------------------------------------------------------------------
// Device scratch (no runtime allocation)
// ---------------------------------------------------------------------------
__device__ float g_z0[NEL];           // fc1(x), time-invariant
__device__ float g_c0[NEL];           // z0 @ w1in^T, time-invariant
__device__ float g_v1[NEL], g_i1[NEL];
__device__ float g_v2[NEL], g_i2[NEL];
__device__ float g_G2[NEL];           // per-step LIF2 input current
__device__ float g_T2[NEL];           // G2 @ w2in^T
__device__ float g_z2[NEL];           // dense z2 (floats 0/1), final output
__device__ float g_w1T[HH * HH];      // w1rec^T  (row k holds w1rec[:,k])
__device__ float g_f2T[HH * HH];      // fc2w^T
__device__ float g_w2T[HH * HH];      // w2rec^T
__device__ unsigned short g_list1[NEL];   // per-row active-index lists
__device__ unsigned short g_list2[NEL];
__device__ int g_c1[BSZ], g_c2[BSZ];
__device__ unsigned g_cnt[TW];

// ---------------------------------------------------------------------------
__global__ void init_state() {
    size_t i = (size_t)blockIdx.x * blockDim.x + threadIdx.x;
    size_t st = (size_t)gridDim.x * blockDim.x;
    for (size_t k = i; k < (size_t)NEL; k += st) {
        g_v1[k] = 0.f; g_i1[k] = 0.f; g_v2[k] = 0.f; g_i2[k] = 0.f;
    }
    for (size_t k = i; k < (size_t)BSZ; k += st) { g_c1[k] = 0; g_c2[k] = 0; }
    if (i < TW) g_cnt[i] = 0u;
}

// ---------------------------------------------------------------------------
// Dense FFMA GEMM (double-buffered, R6-proven):  C = A @ W^T (+bias)
// Per-element fp32 FMA chain, k strictly ascending -> matches reference.
// ---------------------------------------------------------------------------
__global__ __launch_bounds__(NTHR, 2)
void sgemm0(const float* __restrict__ A1, const float* __restrict__ W1,
            const float* __restrict__ bias, float* __restrict__ Cout,
            int K1, int N)
{
    __shared__ __align__(16) float As[2][BK][BM + 4];
    __shared__ __align__(16) float Bs[2][BK][BN + 4];
    const int tid = threadIdx.x, bn = blockIdx.x, bm = blockIdx.y;
    const int tx = tid & 15, ty = tid >> 4;
    const int lrow = tid >> 2, lcol = (tid & 3) << 2;

    float acc[TM][TN];
#pragma unroll
    for (int i = 0; i < TM; ++i)
#pragma unroll
        for (int j = 0; j < TN; ++j) acc[i][j] = 0.f;

    const int ntot = K1 / BK;
    float4 ra0, ra1, rb0, rb1;

    #define LDGT(kt) do {                                                      \
        const float* Ap = A1 + (size_t)(bm * BM + lrow) * K1 + (kt) * BK + lcol;\
        const float* Wp = W1 + (size_t)(bn * BN + lrow) * K1 + (kt) * BK + lcol;\
        ra0 = *(const float4*)Ap; ra1 = *(const float4*)(Ap + (size_t)64 * K1); \
        rb0 = *(const float4*)Wp; rb1 = *(const float4*)(Wp + (size_t)64 * K1); \
    } while (0)
    #define STST(buf) do {                                                     \
        As[buf][lcol+0][lrow]=ra0.x; As[buf][lcol+1][lrow]=ra0.y;              \
        As[buf][lcol+2][lrow]=ra0.z; As[buf][lcol+3][lrow]=ra0.w;              \
        As[buf][lcol+0][lrow+64]=ra1.x; As[buf][lcol+1][lrow+64]=ra1.y;        \
        As[buf][lcol+2][lrow+64]=ra1.z; As[buf][lcol+3][lrow+64]=ra1.w;        \
        Bs[buf][lcol+0][lrow]=rb0.x; Bs[buf][lcol+1][lrow]=rb0.y;              \
        Bs[buf][lcol+2][lrow]=rb0.z; Bs[buf][lcol+3][lrow]=rb0.w;              \
        Bs[buf][lcol+0][lrow+64]=rb1.x; Bs[buf][lcol+1][lrow+64]=rb1.y;        \
        Bs[buf][lcol+2][lrow+64]=rb1.z; Bs[buf][lcol+3][lrow+64]=rb1.w;        \
    } while (0)

    LDGT(0); STST(0); __syncthreads();
    for (int kt = 0; kt < ntot; ++kt) {
        const int cur = kt & 1;
        const bool more = (kt + 1 < ntot);
        if (more) LDGT(kt + 1);
#pragma unroll
        for (int k = 0; k < BK; ++k) {
            const float4 av0 = *(const float4*)&As[cur][k][ty * TM];
            const float4 av1 = *(const float4*)&As[cur][k][ty * TM + 4];
            const float4 bv0 = *(const float4*)&Bs[cur][k][tx * TN];
            const float4 bv1 = *(const float4*)&Bs[cur][k][tx * TN + 4];
            float a[TM] = {av0.x, av0.y, av0.z, av0.w, av1.x, av1.y, av1.z, av1.w};
            float b[TN] = {bv0.x, bv0.y, bv0.z, bv0.w, bv1.x, bv1.y, bv1.z, bv1.w};
#pragma unroll
            for (int i = 0; i < TM; ++i)
#pragma unroll
                for (int j = 0; j < TN; ++j) acc[i][j] += a[i] * b[j];
        }
        if (more) { STST(cur ^ 1); __syncthreads(); }
    }
    const int m0 = bm * BM + ty * TM, n0 = bn * BN + tx * TN;
#pragma unroll
    for (int i = 0; i < TM; ++i) {
        size_t row = (size_t)(m0 + i) * N + n0;
#pragma unroll
        for (int j = 0; j < TN; ++j) {
            float v = acc[i][j];
            if (bias) v += bias[n0 + j];
            Cout[row + j] = v;
        }
    }
}

__global__ void transpose_hh(const float* __restrict__ in, float* __restrict__ out) {
    __shared__ float t[32][33];
    int x = blockIdx.x * 32 + threadIdx.x, y = blockIdx.y * 32 + threadIdx.y;
    for (int j = 0; j < 32; j += 8)
        t[threadIdx.y + j][threadIdx.x] = in[(size_t)(y + j) * HH + x];
    __syncthreads();
    x = blockIdx.y * 32 + threadIdx.x; y = blockIdx.x * 32 + threadIdx.y;
    for (int j = 0; j < 32; j += 8)
        out[(size_t)(y + j) * HH + x] = t[threadIdx.x][threadIdx.y + j];
}

// ---------------------------------------------------------------------------
// Sparse helpers: acc[j] += WT[k][col+j] over active k ASCENDING.
// Bitwise equal to the dense fp32 FMA chain (z=1 adds w exactly; z=0 no-op).
// ---------------------------------------------------------------------------
__device__ __forceinline__ void sparse_accum(float acc[8], const float* __restrict__ WT,
                                             const unsigned short* __restrict__ sl,
                                             int cnt, int col)
{
    int i = 0;
    for (; i + 4 <= cnt; i += 4) {
        const int k0 = sl[i], k1 = sl[i + 1], k2 = sl[i + 2], k3 = sl[i + 3];
        const float4* p0 = (const float4*)(WT + (size_t)k0 * HH + col);
        const float4* p1 = (const float4*)(WT + (size_t)k1 * HH + col);
        const float4* p2 = (const float4*)(WT + (size_t)k2 * HH + col);
        const float4* p3 = (const float4*)(WT + (size_t)k3 * HH + col);
        float4 a0 = p0[0], a1 = p0[1];
        float4 b0 = p1[0], b1 = p1[1];
        float4 c0 = p2[0], c1 = p2[1];
        float4 d0 = p3[0], d1 = p3[1];
        acc[0] += a0.x; acc[1] += a0.y; acc[2] += a0.z; acc[3] += a0.w;
        acc[4] += a1.x; acc[5] += a1.y; acc[6] += a1.z; acc[7] += a1.w;
        acc[0] += b0.x; acc[1] += b0.y; acc[2] += b0.z; acc[3] += b0.w;
        acc[4] += b1.x; acc[5] += b1.y; acc[6] += b1.z; acc[7] += b1.w;
        acc[0] += c0.x; acc[1] += c0.y; acc[2] += c0.z; acc[3] += c0.w;
        acc[4] += c1.x; acc[5] += c1.y; acc[6] += c1.z; acc[7] += c1.w;
        acc[0] += d0.x; acc[1] += d0.y; acc[2] += d0.z; acc[3] += d0.w;
        acc[4] += d1.x; acc[5] += d1.y; acc[6] += d1.z; acc[7] += d1.w;
    }
    for (; i < cnt; ++i) {
        const int k = sl[i];
        const float4* p = (const float4*)(WT + (size_t)k * HH + col);
        float4 a0 = p[0], a1 = p[1];
        acc[0] += a0.x; acc[1] += a0.y; acc[2] += a0.z; acc[3] += a0.w;
        acc[4] += a1.x; acc[5] += a1.y; acc[6] += a1.z; acc[7] += a1.w;
    }
}

// Build ascending active list from per-thread 8-bit masks (thread t owns
// cols t*8..t*8+7; 128 threads, 4 warps). Returns new count.
__device__ __forceinline__ int build_list(unsigned mask, unsigned short* sl,
                                          int* s_w, int lane, int wid, int col)
{
    int myc = __popc(mask);
    int pre = myc;
#pragma unroll
    for (int o = 1; o < 32; o <<= 1) {
        int u = __shfl_up_sync(FULLMASK, pre, o);
        if (lane >= o) pre += u;
    }
    if (lane == 31) s_w[wid] = pre;
    __syncthreads();
    int base = 0;
    for (int w = 0; w < wid; ++w) base += s_w[w];
    int off = base + pre - myc;
#pragma unroll
    for (int j = 0; j < 8; ++j)
        if (mask & (1u << j)) sl[off++] = (unsigned short)(col + j);
    int ncnt = s_w[0] + s_w[1] + s_w[2] + s_w[3];
    __syncthreads();
    return ncnt;
}

// ---------------------------------------------------------------------------
// LIF1 + G2: per batch row m.
//   acc = sum_{k in act(z1_old[m])} w1recT[k][:]      (bitwise dense chain)
//   LIF1 epilogue: v1,i1 update with c0; z1_new
//   G2[m] = sum_{k in act(z1_new[m])} fc2wT[k][:] + fc2b
// ---------------------------------------------------------------------------
__global__ __launch_bounds__(128)
void lif1_step(unsigned short* __restrict__ list, int* __restrict__ lcnt,
               const float* __restrict__ W1T, const float* __restrict__ F2T,
               const float* __restrict__ c0v, const float* __restrict__ bias,
               float* __restrict__ V, float* __restrict__ I,
               float* __restrict__ G2)
{
    __shared__ unsigned short s_list[HH];
    __shared__ int s_w[4];
    const int m = blockIdx.x, t = threadIdx.x;
    const int lane = t & 31, wid = t >> 5;
    const int col = t * 8;
    const size_t ridx = (size_t)m * HH + col;

    int cnt = lcnt[m];
    for (int i = t; i < cnt; i += 128) s_list[i] = list[(size_t)m * HH + i];
    __syncthreads();

    float acc[8];
#pragma unroll
    for (int j = 0; j < 8; ++j) acc[j] = 0.f;
    sparse_accum(acc, W1T, s_list, cnt, col);

    // LIF1 epilogue (expressions identical to the R3/R6 passing kernel)
    float4 v0 = *(const float4*)(V + ridx),   v1 = *(const float4*)(V + ridx + 4);
    float4 i0 = *(const float4*)(I + ridx),   i1 = *(const float4*)(I + ridx + 4);
    float4 q0 = *(const float4*)(c0v + ridx), q1 = *(const float4*)(c0v + ridx + 4);
    float vold[8] = {v0.x, v0.y, v0.z, v0.w, v1.x, v1.y, v1.z, v1.w};
    float iold[8] = {i0.x, i0.y, i0.z, i0.w, i1.x, i1.y, i1.z, i1.w};
    float cin[8]  = {q0.x, q0.y, q0.z, q0.w, q1.x, q1.y, q1.z, q1.w};
    float vn[8], in_[8];
    unsigned mask = 0;
#pragma unroll
    for (int j = 0; j < 8; ++j) {
        float vdec = vold[j] + 0.1f * (iold[j] - vold[j]);
        float z = (vdec > 1.0f) ? 1.0f : 0.0f;
        vn[j] = (1.0f - z) * vdec;
        float idec = iold[j] * 0.8f;
        in_[j] = (idec + cin[j]) + acc[j];
        if (z != 0.0f) mask |= (1u << j);
    }
    *(float4*)(V + ridx)     = make_float4(vn[0], vn[1], vn[2], vn[3]);
    *(float4*)(V + ridx + 4) = make_float4(vn[4], vn[5], vn[6], vn[7]);
    *(float4*)(I + ridx)     = make_float4(in_[0], in_[1], in_[2], in_[3]);
    *(float4*)(I + ridx + 4) = make_float4(in_[4], in_[5], in_[6], in_[7]);

    __syncthreads();   // old s_list fully consumed before overwrite
    int ncnt = build_list(mask, s_list, s_w, lane, wid, col);

    // write new list + count
    for (int i = t; i < ncnt; i += 128) list[(size_t)m * HH + i] = s_list[i];
    if (t == 0) lcnt[m] = ncnt;

    // G2 = sparse sum over z1_new + bias  (ascending, bitwise dense chain)
    float acc2[8];
#pragma unroll
    for (int j = 0; j < 8; ++j) acc2[j] = 0.f;
    sparse_accum(acc2, F2T, s_list, ncnt, col);
    float4 bb0 = *(const float4*)(bias + col), bb1 = *(const float4*)(bias + col + 4);
    float bv[8] = {bb0.x, bb0.y, bb0.z, bb0.w, bb1.x, bb1.y, bb1.z, bb1.w};
    float g[8];
#pragma unroll
    for (int j = 0; j < 8; ++j) { float v = acc2[j]; v += bv[j]; g[j] = v; }
    *(float4*)(G2 + ridx)     = make_float4(g[0], g[1], g[2], g[3]);
    *(float4*)(G2 + ridx + 4) = make_float4(g[4], g[5], g[6], g[7]);
}

// ---------------------------------------------------------------------------
// LIF2: acc starts at T2[m] (= G2@w2in^T chain) and continues with the sparse
// recurrent terms -> bitwise identical to the R3 chained dual-GEMM accumulator.
// ---------------------------------------------------------------------------
__global__ __launch_bounds__(128)
void lif2_step(unsigned short* __restrict__ list, int* __restrict__ lcnt,
               const float* __restrict__ W2T, const float* __restrict__ T2,
               float* __restrict__ V, float* __restrict__ I,
               float* __restrict__ Z2, unsigned* __restrict__ cnt_out)
{
    __shared__ unsigned short s_list[HH];
    __shared__ int s_w[4];
    const int m = blockIdx.x, t = threadIdx.x;
    const int lane = t & 31, wid = t >> 5;
    const int col = t * 8;
    const size_t ridx = (size_t)m * HH + col;

    int cnt = lcnt[m];
    for (int i = t; i < cnt; i += 128) s_list[i] = list[(size_t)m * HH + i];
    __syncthreads();

    float4 t0 = *(const float4*)(T2 + ridx), t1 = *(const float4*)(T2 + ridx + 4);
    float acc[8] = {t0.x, t0.y, t0.z, t0.w, t1.x, t1.y, t1.z, t1.w};
    sparse_accum(acc, W2T, s_list, cnt, col);

    float4 v0 = *(const float4*)(V + ridx), v1 = *(const float4*)(V + ridx + 4);
    float4 i0 = *(const float4*)(I + ridx), i1 = *(const float4*)(I + ridx + 4);
    float vold[8] = {v0.x, v0.y, v0.z, v0.w, v1.x, v1.y, v1.z, v1.w};
    float iold[8] = {i0.x, i0.y, i0.z, i0.w, i1.x, i1.y, i1.z, i1.w};
    float vn[8], in_[8], zn[8];
    unsigned mask = 0;
#pragma unroll
    for (int j = 0; j < 8; ++j) {
        float vdec = vold[j] + 0.1f * (iold[j] - vold[j]);
        float z = (vdec > 1.0f) ? 1.0f : 0.0f;
        vn[j] = (1.0f - z) * vdec;
        float idec = iold[j] * 0.8f;
        in_[j] = idec + acc[j];
        zn[j] = z;
        if (z != 0.0f) mask |= (1u << j);
    }
    *(float4*)(V + ridx)     = make_float4(vn[0], vn[1], vn[2], vn[3]);
    *(float4*)(V + ridx + 4) = make_float4(vn[4], vn[5], vn[6], vn[7]);
    *(float4*)(I + ridx)     = make_float4(in_[0], in_[1], in_[2], in_[3]);
    *(float4*)(I + ridx + 4) = make_float4(in_[4], in_[5], in_[6], in_[7]);
    *(float4*)(Z2 + ridx)     = make_float4(zn[0], zn[1], zn[2], zn[3]);
    *(float4*)(Z2 + ridx + 4) = make_float4(zn[4], zn[5], zn[6], zn[7]);

    __syncthreads();
    int ncnt = build_list(mask, s_list, s_w, lane, wid, col);
    for (int i = t; i < ncnt; i += 128) list[(size_t)m * HH + i] = s_list[i];
    if (t == 0) {
        lcnt[m] = ncnt;
        atomicAdd(cnt_out, (unsigned)ncnt);
    }
}

// ---------------------------------------------------------------------------
__global__ void finalize(const float* __restrict__ zlast,
                         const unsigned* __restrict__ cnt,
                         float* __restrict__ out, int n, int out_size)
{
    size_t i = (size_t)blockIdx.x * blockDim.x + threadIdx.x;
    size_t st = (size_t)gridDim.x * blockDim.x;
    for (size_t k = i; k < (size_t)n; k += st) out[k] = zlast[k];
    if (i == 0 && out_size > n) {
        float rs = 0.f;
        for (int t = 0; t < TW; ++t)
            rs += (float)cnt[t] * (1.0f / 4194304.0f);   // exact: /2^22
        out[n] = rs * (1.0f / 16.0f);                     // inv_T, exact
    }
}

// ---------------------------------------------------------------------------
extern "C" void kernel_launch(void* const* d_in, const int* in_sizes, int n_in,
                              void* d_out, int out_size)
{
    const float* x     = (const float*)d_in[0];
    const float* fc1w  = (const float*)d_in[1];
    const float* fc1b  = (const float*)d_in[2];
    const float* w1in  = (const float*)d_in[3];
    const float* w1rec = (const float*)d_in[4];
    const float* fc2w  = (const float*)d_in[5];
    const float* fc2b  = (const float*)d_in[6];
    const float* w2in  = (const float*)d_in[7];
    const float* w2rec = (const float*)d_in[8];
    (void)in_sizes; (void)n_in;

    float *z0, *c0, *v1, *i1, *v2, *i2, *G2, *T2, *z2, *w1T, *f2T, *w2T;
    unsigned short *l1, *l2;
    int *c1, *c2;
    unsigned* cnt;
    cudaGetSymbolAddress((void**)&z0, g_z0);
    cudaGetSymbolAddress((void**)&c0, g_c0);
    cudaGetSymbolAddress((void**)&v1, g_v1);
    cudaGetSymbolAddress((void**)&i1, g_i1);
    cudaGetSymbolAddress((void**)&v2, g_v2);
    cudaGetSymbolAddress((void**)&i2, g_i2);
    cudaGetSymbolAddress((void**)&G2, g_G2);
    cudaGetSymbolAddress((void**)&T2, g_T2);
    cudaGetSymbolAddress((void**)&z2, g_z2);
    cudaGetSymbolAddress((void**)&w1T, g_w1T);
    cudaGetSymbolAddress((void**)&f2T, g_f2T);
    cudaGetSymbolAddress((void**)&w2T, g_w2T);
    cudaGetSymbolAddress((void**)&l1, g_list1);
    cudaGetSymbolAddress((void**)&l2, g_list2);
    cudaGetSymbolAddress((void**)&c1, g_c1);
    cudaGetSymbolAddress((void**)&c2, g_c2);
    cudaGetSymbolAddress((void**)&cnt, g_cnt);

    dim3 grid(HH / BN, BSZ / BM);   // (8, 32)
    dim3 tgrid(32, 32), tblk(32, 8);

    init_state<<<256, 256>>>();

    // ---- one-time prologue ----
    sgemm0<<<grid, NTHR>>>(x, fc1w, fc1b, z0, DD, HH);   // z0 = fc1(x)
    sgemm0<<<grid, NTHR>>>(z0, w1in, nullptr, c0, HH, HH); // c0 = z0@w1in^T
    transpose_hh<<<tgrid, tblk>>>(w1rec, w1T);
    transpose_hh<<<tgrid, tblk>>>(fc2w,  f2T);
    transpose_hh<<<tgrid, tblk>>>(w2rec, w2T);

    // ---- time loop: sparse LIF1+G2, dense T2, sparse LIF2 ----
    for (int t = 0; t < TW; ++t) {
        lif1_step<<<BSZ, 128>>>(l1, c1, w1T, f2T, c0, fc2b, v1, i1, G2);
        sgemm0<<<grid, NTHR>>>(G2, w2in, nullptr, T2, HH, HH);
        lif2_step<<<BSZ, 128>>>(l2, c2, w2T, T2, v2, i2, z2, cnt + t);
    }

    finalize<<<512, 256>>>(z2, cnt, (float*)d_out, NEL, out_size);
}